// round 11
// baseline (speedup 1.0000x reference)
#include <cuda_runtime.h>
#include <cuda_fp16.h>
#include <math.h>
#include <stdint.h>

#define NB 4
#define NL 4096
#define NC 1024
#define NH 8
#define NR 512
#define ND 64
#define LAMBDA_INIT 0.8f
#define EPS 1e-6f

#define SZQ   (NB*NH*NR*ND)
#define SSZ   (NB*NH*NR*NR)

// ======================= device scratch (no allocs allowed) ==================
__device__ __half g_xd [NB*NR*NC];
__device__ __half g_W  [3*NC*NC];          // Wq,Wk,Wv
__device__ __half g_Wo [NC*NC];
__device__ __half g_q12[2*SZQ];
__device__ __half g_k12[2*SZQ];
__device__ __half g_vt [NB*NH*128*NR];
__device__ float  g_s12[2*SSZ];
__device__ __half g_p  [SSZ];
__device__ __half g_y  [NB*NR*NC];
__device__ float  g_lam[1];

// ======================= asm helpers =========================================
__device__ __forceinline__ uint32_t smem_u32(const void* p){
    uint32_t a;
    asm("{ .reg .u64 t; cvta.to.shared.u64 t, %1; cvt.u32.u64 %0, t; }" : "=r"(a) : "l"(p));
    return a;
}
__device__ __forceinline__ void cpa16(uint32_t d, const void* s){
    asm volatile("cp.async.cg.shared.global [%0], [%1], 16;" :: "r"(d), "l"(s));
}
#define CP_COMMIT() asm volatile("cp.async.commit_group;" ::: "memory")
#define CP_WAIT0()  asm volatile("cp.async.wait_group 0;" ::: "memory")
#define CP_WAIT1()  asm volatile("cp.async.wait_group 1;" ::: "memory")

__device__ __forceinline__ void mma16816(float* c,
    uint32_t a0, uint32_t a1, uint32_t a2, uint32_t a3, uint32_t b0, uint32_t b1)
{
    asm volatile(
        "mma.sync.aligned.m16n8k16.row.col.f32.f16.f16.f32 "
        "{%0,%1,%2,%3}, {%4,%5,%6,%7}, {%8,%9}, {%0,%1,%2,%3};"
        : "+f"(c[0]), "+f"(c[1]), "+f"(c[2]), "+f"(c[3])
        : "r"(a0), "r"(a1), "r"(a2), "r"(a3), "r"(b0), "r"(b1));
}
#define LDSM4(r0,r1,r2,r3, addr) \
    asm volatile("ldmatrix.sync.aligned.m8n8.x4.shared.b16 {%0,%1,%2,%3}, [%4];" \
        : "=r"(r0),"=r"(r1),"=r"(r2),"=r"(r3) : "r"(addr))

__device__ __forceinline__ unsigned short h1(float v){
    return __half_as_ushort(__float2half_rn(v));
}

// ======================= HMMA fp16 batched NT GEMM ===========================
// BK=64, rows 144B (128B data + 16B pad), 3-stage cp.async, 2 CTAs/SM.
// Mainloop: 16-step flat (kk,mi) schedule, A frags double-buffered per step,
// B frags double-buffered per kk -> every LDSM has >=4 MMA-issues of slack.
// mode 0: C = alpha*acc   1: silu   2: PV headnorm->g_y   3: QKV fused epilogue
#define ROW_B   144
#define TILE_B  (128*ROW_B)          // 18432
#define STG_B   (2*TILE_B)           // A+B = 36864
#define GEMM_SMEM (3*STG_B)          // 110592 -> 2 CTAs/SM

__device__ __forceinline__ void ld_stage(uint32_t sbase, int tid, long long c64,
    const __half* Ab, const __half* Bb, int K)
{
    int seg = tid & 7;
    #pragma unroll
    for (int it = 0; it < 8; it++) {
        int i = tid + it*256;
        int r = (i >> 3) & 127;
        const __half* src = (it < 4) ? Ab : Bb;
        cpa16(sbase + (it >> 2)*TILE_B + r*ROW_B + seg*16,
              src + (long long)r*K + c64 + seg*8);
    }
    CP_COMMIT();
}

__global__ __launch_bounds__(256, 2)
void gemm_mma(const __half* __restrict__ A, const __half* __restrict__ B,
              float* __restrict__ C, int M, int N, int K,
              long long sA, long long sB, long long sC, float alpha, int mode,
              const float* __restrict__ w1, const float* __restrict__ w2)
{
    extern __shared__ char sm[];
    uint32_t sb = smem_u32(sm);
    const int tid  = threadIdx.x;
    const int wid  = tid >> 5, lane = tid & 31;
    const int gid  = lane >> 2, tig = lane & 3;
    const int wm   = (wid & 1) * 64;
    const int wn   = (wid >> 1) * 32;
    const int bm   = blockIdx.y * 128, bn = blockIdx.x * 128;
    const int z    = blockIdx.z;

    const __half* Ab = A + z*sA + (long long)bm*K;
    const __half* Bb = B + z*sB + (long long)bn*K;

    const int a_row = (lane & 7) + ((lane & 8)  ? 8 : 0);
    const int a_col = (lane & 16) ? 16 : 0;
    const int b_row = (lane & 7) + ((lane & 16) ? 8 : 0);
    const int b_col = (lane & 8)  ? 16 : 0;

    float acc[4][4][4];
    #pragma unroll
    for (int mi = 0; mi < 4; mi++)
        #pragma unroll
        for (int ni = 0; ni < 4; ni++)
            #pragma unroll
            for (int t = 0; t < 4; t++) acc[mi][ni][t] = 0.f;

    const int nch = K >> 6;
    ld_stage(sb, tid, 0, Ab, Bb, K);
    if (nch > 1) ld_stage(sb + STG_B, tid, 64, Ab, Bb, K);

    uint32_t ah[2][4];        // A frags, double-buffered per step
    uint32_t bh[2][4][2];     // B frags, double-buffered per kk

    for (int c = 0; c < nch; c++) {
        if (c + 1 < nch) CP_WAIT1(); else CP_WAIT0();
        __syncthreads();                       // stage c ready; c-1 consumed
        if (c + 2 < nch)
            ld_stage(sb + ((c + 2) % 3)*STG_B, tid, (long long)(c + 2)*64, Ab, Bb, K);

        const uint32_t p  = sb + (c % 3)*STG_B;
        const uint32_t pA = p, pB = p + TILE_B;

        // prologue: B(kk=0), A(step=0)
        #pragma unroll
        for (int nj = 0; nj < 2; nj++) {
            uint32_t bd = pB + (wn + nj*16 + b_row)*ROW_B + 0 + b_col;
            LDSM4(bh[0][2*nj][0], bh[0][2*nj][1], bh[0][2*nj+1][0], bh[0][2*nj+1][1], bd);
        }
        {
            uint32_t ad = pA + (wm + 0*16 + a_row)*ROW_B + 0 + a_col;
            LDSM4(ah[0][0], ah[0][1], ah[0][2], ah[0][3], ad);
        }

        #pragma unroll
        for (int st = 0; st < 16; st++) {
            const int kk = st >> 2, mi = st & 3;
            const int cb = st & 1;
            // issue B for kk+1 at the start of each kk
            if (mi == 0 && kk < 3) {
                const int nb = (kk + 1) & 1;
                #pragma unroll
                for (int nj = 0; nj < 2; nj++) {
                    uint32_t bd = pB + (wn + nj*16 + b_row)*ROW_B + (kk+1)*32 + b_col;
                    LDSM4(bh[nb][2*nj][0], bh[nb][2*nj][1],
                          bh[nb][2*nj+1][0], bh[nb][2*nj+1][1], bd);
                }
            }
            // issue A for step+1
            if (st < 15) {
                const int nk = (st + 1) >> 2, nm = (st + 1) & 3, nb = (st + 1) & 1;
                uint32_t ad = pA + (wm + nm*16 + a_row)*ROW_B + nk*32 + a_col;
                LDSM4(ah[nb][0], ah[nb][1], ah[nb][2], ah[nb][3], ad);
            }
            // 4 MMAs for this step
            const int kb = kk & 1;
            #pragma unroll
            for (int ni = 0; ni < 4; ni++)
                mma16816(acc[mi][ni], ah[cb][0], ah[cb][1], ah[cb][2], ah[cb][3],
                         bh[kb][ni][0], bh[kb][ni][1]);
        }
    }

    if (mode == 0 || mode == 1) {
        float* Cb = C + z*sC;
        #pragma unroll
        for (int mi = 0; mi < 4; mi++) {
            #pragma unroll
            for (int ni = 0; ni < 4; ni++) {
                int row = bm + wm + mi*16 + gid;
                int col = bn + wn + ni*8 + tig*2;
                float v0 = acc[mi][ni][0]*alpha, v1 = acc[mi][ni][1]*alpha;
                float v2 = acc[mi][ni][2]*alpha, v3 = acc[mi][ni][3]*alpha;
                if (mode == 1) {
                    v0 /= (1.f + __expf(-v0)); v1 /= (1.f + __expf(-v1));
                    v2 /= (1.f + __expf(-v2)); v3 /= (1.f + __expf(-v3));
                }
                *(float2*)&Cb[(long long)row*N + col]       = make_float2(v0, v1);
                *(float2*)&Cb[(long long)(row + 8)*N + col] = make_float2(v2, v3);
            }
        }
        return;
    }

    // ---------- stage accumulators to smem (row-major, or transposed for v) ---
    __syncthreads();                            // mainloop smem reads done
    float* esm = (float*)sm;                    // 128 x 132 floats
    const bool vtr = (mode == 3 && z == 2);
    #pragma unroll
    for (int mi = 0; mi < 4; mi++) {
        #pragma unroll
        for (int ni = 0; ni < 4; ni++) {
            int r0 = wm + mi*16 + gid;
            int cc = wn + ni*8 + tig*2;
            if (vtr) {
                esm[cc*132 + r0]         = acc[mi][ni][0];
                esm[(cc+1)*132 + r0]     = acc[mi][ni][1];
                esm[cc*132 + r0 + 8]     = acc[mi][ni][2];
                esm[(cc+1)*132 + r0 + 8] = acc[mi][ni][3];
            } else {
                esm[r0*132 + cc]         = acc[mi][ni][0];
                esm[r0*132 + cc + 1]     = acc[mi][ni][1];
                esm[(r0+8)*132 + cc]     = acc[mi][ni][2];
                esm[(r0+8)*132 + cc + 1] = acc[mi][ni][3];
            }
        }
    }
    __syncthreads();

    if (mode == 2) {
        // fused head rmsnorm (PV): z = b*8+h
        const int b = z >> 3, h = z & 7;
        for (int r = wid; r < 128; r += 8) {
            float4 vv = *(float4*)&esm[r*132 + lane*4];
            float ssq = vv.x*vv.x + vv.y*vv.y + vv.z*vv.z + vv.w*vv.w;
            #pragma unroll
            for (int o = 16; o; o >>= 1) ssq += __shfl_xor_sync(0xffffffffu, ssq, o);
            float inv = (1.f - LAMBDA_INIT) * rsqrtf(ssq*(1.f/128.f) + EPS);
            float4 w = ((const float4*)w1)[lane];
            ushort4 hh;
            hh.x = h1(vv.x*inv*w.x); hh.y = h1(vv.y*inv*w.y);
            hh.z = h1(vv.z*inv*w.z); hh.w = h1(vv.w*inv*w.w);
            int i = bm + r;
            long long o4 = (long long)(b*NR + i)*256 + h*32 + lane;
            ((ushort4*)g_y)[o4] = hh;
        }
        return;
    }

    // ---------- mode 3: fused QKV epilogue ------------------------------------
    const int h = blockIdx.x;              // tile cols = one head
    if (z < 2) {
        // rmsnorm(64) + rope(pos=h) + fp16 -> q12 / k12
        const float* w = z ? w2 : w1;
        const int gidx = lane & 15, sgi = lane >> 4;
        const int dmb = (gidx & 7) * 4;
        float4 wv = ((const float4*)w)[gidx];
        float sn[4], cs[4];
        #pragma unroll
        for (int j = 0; j < 4; j++) {
            float f = exp2f(-0.41524101186351494f * (float)(dmb + j));
            __sincosf((float)h * f, &sn[j], &cs[j]);
        }
        __half* dh = (z == 0 ? g_q12 : g_k12) + (long long)sgi*SZQ;
        const bool lo = (gidx & 8) == 0;
        for (int r = wid; r < 128; r += 8) {
            float4 xv = *(float4*)&esm[r*132 + sgi*64 + gidx*4];
            float ssq = xv.x*xv.x + xv.y*xv.y + xv.z*xv.z + xv.w*xv.w;
            #pragma unroll
            for (int o = 8; o; o >>= 1) ssq += __shfl_xor_sync(0xffffffffu, ssq, o);
            float inv = rsqrtf(ssq*(1.f/64.f) + EPS);
            float n0 = xv.x*inv*wv.x, n1 = xv.y*inv*wv.y;
            float n2 = xv.z*inv*wv.z, n3 = xv.w*inv*wv.w;
            float p0 = __shfl_xor_sync(0xffffffffu, n0, 8);
            float p1 = __shfl_xor_sync(0xffffffffu, n1, 8);
            float p2 = __shfl_xor_sync(0xffffffffu, n2, 8);
            float p3 = __shfl_xor_sync(0xffffffffu, n3, 8);
            ushort4 hh;
            hh.x = h1(lo ? n0*cs[0] - p0*sn[0] : p0*sn[0] + n0*cs[0]);
            hh.y = h1(lo ? n1*cs[1] - p1*sn[1] : p1*sn[1] + n1*cs[1]);
            hh.z = h1(lo ? n2*cs[2] - p2*sn[2] : p2*sn[2] + n2*cs[2]);
            hh.w = h1(lo ? n3*cs[3] - p3*sn[3] : p3*sn[3] + n3*cs[3]);
            int tok = bm + r, b = tok >> 9, il = tok & 511;
            long long off = ((long long)((b*NH + h)*NR) + il)*64 + gidx*4;
            *(ushort4*)(dh + off) = hh;
        }
    } else {
        // v: transposed fp16 write -> g_vt  (esm staged transposed)
        const int b = bm >> 9, ibase = bm & 511;
        const int bh2 = b*NH + h;
        #pragma unroll
        for (int it = 0; it < 32; it++) {
            int e = tid + it*256;
            int cix = e >> 6, ip = e & 63, i = ip*2;
            float2 vv = *(float2*)&esm[cix*132 + i];
            long long o = ((long long)(bh2*128 + cix))*NR + ibase + i;
            *(ushort2*)(g_vt + o) = make_ushort2(h1(vv.x), h1(vv.y));
        }
    }
}

// ======================= elementwise kernels =================================
__global__ void downsample_h(const float4* __restrict__ x, ushort4* __restrict__ xd)
{
    int idx = blockIdx.x*blockDim.x + threadIdx.x;
    if (idx >= NB*NR*NC/4) return;
    int c4 = idx & 255, bi = idx >> 8;
    int i = bi & (NR-1), b = bi >> 9;
    long long row = (long long)b*NL + 8*i + 3;
    float4 p = x[row*256 + c4], q = x[(row+1)*256 + c4];
    ushort4 h;
    h.x = h1(0.5f*(p.x+q.x)); h.y = h1(0.5f*(p.y+q.y));
    h.z = h1(0.5f*(p.z+q.z)); h.w = h1(0.5f*(p.w+q.w));
    xd[idx] = h;
}

__global__ void convert4(const float4* __restrict__ Wq, const float4* __restrict__ Wk,
                         const float4* __restrict__ Wv, const float4* __restrict__ Wo,
                         ushort4* __restrict__ w3, ushort4* __restrict__ wo)
{
    int idx = blockIdx.x*blockDim.x + threadIdx.x;
    if (idx >= NC*NC/4) return;
    const float4* s; ushort4* d; int off = 0;
    switch (blockIdx.y) {
        case 0: s = Wq; d = w3; off = 0;          break;
        case 1: s = Wk; d = w3; off = NC*NC/4;    break;
        case 2: s = Wv; d = w3; off = 2*(NC*NC/4);break;
        default:s = Wo; d = wo; off = 0;          break;
    }
    float4 v = s[idx];
    ushort4 h;
    h.x = h1(v.x); h.y = h1(v.y); h.z = h1(v.z); h.w = h1(v.w);
    d[off + idx] = h;
}

__global__ void lambda_kernel(const float* lq1, const float* lk1,
                              const float* lq2, const float* lk2, float* out)
{
    int t = threadIdx.x;
    float a = lq1[t]*lk1[t] + lq1[t+32]*lk1[t+32];
    float b = lq2[t]*lk2[t] + lq2[t+32]*lk2[t+32];
    #pragma unroll
    for (int o = 16; o; o >>= 1) {
        a += __shfl_xor_sync(0xffffffffu, a, o);
        b += __shfl_xor_sync(0xffffffffu, b, o);
    }
    if (t == 0) out[0] = expf(a) - expf(b) + LAMBDA_INIT;
}

// dual softmax + combine -> fp16 probs
__global__ void softmax_combine(const float* __restrict__ s12,
                                const float* __restrict__ lamp,
                                ushort4* __restrict__ ph)
{
    int gw   = (blockIdx.x*blockDim.x + threadIdx.x) >> 5;
    int lane = threadIdx.x & 31;
    if (gw >= NB*NH*NR) return;
    const float4* r1 = (const float4*)(s12 + (long long)gw * NR);
    const float4* r2 = (const float4*)(s12 + (long long)SSZ + (long long)gw * NR);
    float4 v1[4], v2[4];
    float m1 = -1e30f, m2 = -1e30f;
    #pragma unroll
    for (int i = 0; i < 4; i++) {
        v1[i] = r1[lane + 32*i]; v2[i] = r2[lane + 32*i];
        m1 = fmaxf(m1, fmaxf(fmaxf(v1[i].x, v1[i].y), fmaxf(v1[i].z, v1[i].w)));
        m2 = fmaxf(m2, fmaxf(fmaxf(v2[i].x, v2[i].y), fmaxf(v2[i].z, v2[i].w)));
    }
    #pragma unroll
    for (int o = 16; o; o >>= 1) {
        m1 = fmaxf(m1, __shfl_xor_sync(0xffffffffu, m1, o));
        m2 = fmaxf(m2, __shfl_xor_sync(0xffffffffu, m2, o));
    }
    float a1 = 0.f, a2 = 0.f;
    #pragma unroll
    for (int i = 0; i < 4; i++) {
        v1[i].x = __expf(v1[i].x-m1); v1[i].y = __expf(v1[i].y-m1);
        v1[i].z = __expf(v1[i].z-m1); v1[i].w = __expf(v1[i].w-m1);
        v2[i].x = __expf(v2[i].x-m2); v2[i].y = __expf(v2[i].y-m2);
        v2[i].z = __expf(v2[i].z-m2); v2[i].w = __expf(v2[i].w-m2);
        a1 += v1[i].x+v1[i].y+v1[i].z+v1[i].w;
        a2 += v2[i].x+v2[i].y+v2[i].z+v2[i].w;
    }
    #pragma unroll
    for (int o = 16; o; o >>= 1) {
        a1 += __shfl_xor_sync(0xffffffffu, a1, o);
        a2 += __shfl_xor_sync(0xffffffffu, a2, o);
    }
    float is1 = 1.f/a1, is2 = lamp[0]/a2;
    #pragma unroll
    for (int i = 0; i < 4; i++) {
        ushort4 h;
        h.x = h1(v1[i].x*is1 - v2[i].x*is2);
        h.y = h1(v1[i].y*is1 - v2[i].y*is2);
        h.z = h1(v1[i].z*is1 - v2[i].z*is2);
        h.w = h1(v1[i].w*is1 - v2[i].w*is2);
        ph[(long long)gw*128 + lane + 32*i] = h;
    }
}

// upsample 512 -> 4096
__global__ void upsample_kernel(const float4* __restrict__ lr, float4* __restrict__ out)
{
    int idx = blockIdx.x*blockDim.x + threadIdx.x;
    if (idx >= NB*NL*NC/4) return;
    int c4 = idx & 255, j = (idx >> 8) & (NL-1), b = idx >> 20;
    float coords = fminf(fmaxf(((float)j + 0.5f)*0.125f - 0.5f, 0.f), 511.f);
    int lo = (int)coords;
    int hi = min(lo + 1, 511);
    float w = coords - (float)lo, w0 = 1.f - w;
    long long base = (long long)b * NR * 256;
    float4 a = lr[base + (long long)lo*256 + c4];
    float4 c = lr[base + (long long)hi*256 + c4];
    float4 o;
    o.x = a.x*w0 + c.x*w; o.y = a.y*w0 + c.y*w;
    o.z = a.z*w0 + c.z*w; o.w = a.w*w0 + c.w*w;
    out[idx] = o;
}

// ======================= host launcher =======================================
extern "C" void kernel_launch(void* const* d_in, const int* in_sizes, int n_in,
                              void* d_out, int out_size)
{
    const float* x   = (const float*)d_in[0];
    const float* Wq  = (const float*)d_in[1];
    const float* Wk  = (const float*)d_in[2];
    const float* Wv  = (const float*)d_in[3];
    const float* Wo  = (const float*)d_in[4];
    const float* qw  = (const float*)d_in[5];
    const float* kw  = (const float*)d_in[6];
    const float* hw  = (const float*)d_in[7];
    const float* lq1 = (const float*)d_in[8];
    const float* lk1 = (const float*)d_in[9];
    const float* lq2 = (const float*)d_in[10];
    const float* lk2 = (const float*)d_in[11];

    float* full_out = (float*)d_out;
    float* lowrank  = full_out + (size_t)NB*NL*NC;

    #define GS(p, s) cudaGetSymbolAddress((void**)&p, s)
    __half *xd,*W,*Wo_,*q12,*k12,*vt,*pp,*y;
    float *s12,*lam;
    GS(xd,g_xd); GS(W,g_W); GS(Wo_,g_Wo);
    GS(q12,g_q12); GS(k12,g_k12); GS(vt,g_vt);
    GS(s12,g_s12); GS(pp,g_p); GS(y,g_y); GS(lam,g_lam);
    #undef GS

    cudaFuncSetAttribute(gemm_mma, cudaFuncAttributeMaxDynamicSharedMemorySize, GEMM_SMEM);

    // 1. downsample + fp16; weights fp16; lambda
    downsample_h<<<(NB*NR*NC/4 + 255)/256, 256>>>((const float4*)x, (ushort4*)xd);
    dim3 gcv((NC*NC/4 + 255)/256, 4);
    convert4<<<gcv, 256>>>((const float4*)Wq, (const float4*)Wk,
                           (const float4*)Wv, (const float4*)Wo,
                           (ushort4*)W, (ushort4*)Wo_);
    lambda_kernel<<<1, 32>>>(lq1, lk1, lq2, lk2, lam);

    // 2. QKV projections with fused normrope (z<2) / v-transpose (z=2) epilogues
    dim3 gqkv(NC/128, (NB*NR)/128, 3);
    gemm_mma<<<gqkv, 256, GEMM_SMEM>>>(xd, W, nullptr, NB*NR, NC, NC,
        0, (long long)NC*NC, 0, 1.f, 3, qw, kw);

    // 3. both score GEMMs in one launch (z in [0,64) spans s1|s2)
    dim3 gsc(NR/128, NR/128, 2*NB*NH);
    gemm_mma<<<gsc, 256, GEMM_SMEM>>>(q12, k12, s12, NR, NR, ND,
        (long long)NR*ND, (long long)NR*ND, (long long)NR*NR, 0.125f, 0, nullptr, nullptr);

    // 4. dual softmax + combine -> fp16 probs
    softmax_combine<<<(NB*NH*NR*32 + 255)/256, 256>>>(s12, lam, (ushort4*)pp);

    // 5. PV GEMM with fused head rmsnorm -> g_y
    dim3 gpv(1, NR/128, NB*NH);
    gemm_mma<<<gpv, 256, GEMM_SMEM>>>(pp, vt, nullptr, NR, 128, NR,
        (long long)NR*NR, (long long)128*NR, 0, 1.f, 2, hw, nullptr);

    // 6. Wo projection + fused silu -> lowrank_out
    dim3 gwo(NC/128, (NB*NR)/128, 1);
    gemm_mma<<<gwo, 256, GEMM_SMEM>>>(y, Wo_, lowrank, NB*NR, NC, NC,
        0, 0, 0, 1.f, 1, nullptr, nullptr);

    // 7. upsample -> full_out
    upsample_kernel<<<(NB*NL*NC/4 + 255)/256, 256>>>((const float4*)lowrank, (float4*)full_out);
}